// round 7
// baseline (speedup 1.0000x reference)
#include <cuda_runtime.h>
#include <cuda_fp16.h>
#include <cstdint>
#include <math.h>

#define B 256
#define D 512
#define P 5
#define NCLS 11003
#define NPAD 11008        // 86 * 128
#define SEGC 6
#define HH 4096           // 64*64
#define NPIX (1280*4096)  // B*P*H*H
#define SCALE 28.0f
#define ALPHA 0.6f
#define BETA 0.4f
#define SPC 10.0f
#define SNC 40.0f
#define TOPK 8
#define M_TOT 512         // 256 visual rows + 256 textual rows

// ---------------- scratch (device globals; no allocation) ----------------
__device__ float d_An[M_TOT * D];                  // rows 0..255 = vn, 256..511 = tn
__device__ __align__(16) __half d_Af16[M_TOT * D];
__device__ __align__(16) __half d_Wtf16[NPAD * D]; // [n][k] transposed, invw-scaled
__device__ float d_pen[P * B * D];
__device__ float d_aen[P * B * D];
__device__ float d_invw[NPAD];
__device__ float d_rowsum[M_TOT];
__device__ float d_lablogit[M_TOT];
__device__ float d_sim[6 * B * B];
__device__ int   d_boost1[P * B];
__device__ int   d_boost2[P * B];
__device__ float d_acc[8];                         // 0: mask, 1: global, 2: local

__device__ __forceinline__ float softplusf(float x) {
    return fmaxf(x, 0.f) + log1pf(expf(-fabsf(x)));
}

__device__ __forceinline__ uint32_t smem_u32(const void* p) {
    uint32_t a;
    asm("{ .reg .u64 t; cvta.to.shared.u64 t, %1; cvt.u32.u64 %0, t; }" : "=r"(a) : "l"(p));
    return a;
}
__device__ __forceinline__ void cp16(uint32_t s, const void* g) {
    asm volatile("cp.async.cg.shared.global [%0], [%1], 16;" :: "r"(s), "l"(g));
}
#define CP_COMMIT() asm volatile("cp.async.commit_group;" ::: "memory")
#define CP_WAIT(n)  asm volatile("cp.async.wait_group %0;" :: "n"(n) : "memory")

#define LDSM4(r0, r1, r2, r3, addr) \
    asm volatile("ldmatrix.sync.aligned.m8n8.x4.shared.b16 {%0,%1,%2,%3}, [%4];" \
                 : "=r"(r0), "=r"(r1), "=r"(r2), "=r"(r3) : "r"(addr))

#define MMA16816F(d, a, b0, b1) \
    asm volatile("mma.sync.aligned.m16n8k16.row.col.f32.f16.f16.f32 " \
                 "{%0,%1,%2,%3},{%4,%5,%6,%7},{%8,%9},{%0,%1,%2,%3};" \
                 : "+f"((d)[0]), "+f"((d)[1]), "+f"((d)[2]), "+f"((d)[3]) \
                 : "r"((a)[0]), "r"((a)[1]), "r"((a)[2]), "r"((a)[3]), "r"(b0), "r"(b1))

// ---------------- init ----------------
__global__ void k_init() {
    int t = threadIdx.x;
    if (t < M_TOT) d_rowsum[t] = 0.f;
    if (t < 8) d_acc[t] = 0.f;
}

// ---------------- normalize all embedding rows (+ fp16 for An) ----------------
__global__ void k_normalize(const float* __restrict__ vis, const float* __restrict__ txt,
                            const float* __restrict__ pe, const float* __restrict__ ae) {
    int warp = (blockIdx.x * blockDim.x + threadIdx.x) >> 5;
    int lane = threadIdx.x & 31;
    if (warp >= 3072) return;
    const float* src;
    float* dst;
    if (warp < 256)       { src = vis + warp * D;            dst = d_An  + warp * D; }
    else if (warp < 512)  { src = txt + (warp - 256) * D;    dst = d_An  + warp * D; }
    else if (warp < 1792) { src = pe  + (warp - 512) * D;    dst = d_pen + (warp - 512) * D; }
    else                  { src = ae  + (warp - 1792) * D;   dst = d_aen + (warp - 1792) * D; }
    float ss = 0.f;
    for (int d = lane; d < D; d += 32) { float x = src[d]; ss += x * x; }
    #pragma unroll
    for (int o = 16; o > 0; o >>= 1) ss += __shfl_xor_sync(0xffffffff, ss, o);
    float inv = rsqrtf(ss);
    if (warp < 512) {
        for (int d = lane; d < D; d += 32) {
            float x = src[d] * inv;
            dst[d] = x;
            d_Af16[warp * D + d] = __float2half_rn(x);
        }
    } else {
        for (int d = lane; d < D; d += 32) dst[d] = src[d] * inv;
    }
}

// ---------------- W prep: column norms + fp16 transpose + invw scale (merged) ----------------
// grid 86 blocks x 512 threads; block owns 128 n-columns, all K.
__global__ void __launch_bounds__(512)
k_wprep(const float* __restrict__ W) {
    __shared__ float red[4][128];
    __shared__ float sInv[128];
    __shared__ float S[64][129];
    int t = threadIdx.x;
    int n0 = blockIdx.x * 128;
    // phase 1: column sumsq (4 k-strips x 128 cols)
    {
        int c = t & 127;
        int ks = t >> 7;
        int n = n0 + c;
        float ss = 0.f;
        if (n < NCLS) {
            for (int k = ks * 128; k < ks * 128 + 128; k++) {
                float x = W[k * NCLS + n];
                ss += x * x;
            }
        }
        red[ks][c] = ss;
        __syncthreads();
        if (t < 128) {
            float s = red[0][c] + red[1][c] + red[2][c] + red[3][c];
            float iv = ((n0 + c) < NCLS) ? rsqrtf(s) : 0.f;
            sInv[c] = iv;
            d_invw[n0 + c] = iv;
        }
        __syncthreads();
    }
    // phase 2: 8 k-tiles of 64, transpose to [n][k] fp16
    for (int kt = 0; kt < 8; kt++) {
        #pragma unroll
        for (int i = 0; i < 16; i++) {
            int idx = t + (i << 9);
            int kk = idx >> 7;
            int c = idx & 127;
            int n = n0 + c;
            S[kk][c] = (n < NCLS) ? W[(kt * 64 + kk) * NCLS + n] : 0.f;
        }
        __syncthreads();
        #pragma unroll
        for (int i = 0; i < 2; i++) {
            int it = t + (i << 9);
            int row = it >> 3;           // 0..127
            int ch = it & 7;             // 8 fp16 = 16B
            float iv = sInv[row];
            __half h8[8];
            #pragma unroll
            for (int j = 0; j < 8; j++)
                h8[j] = __float2half_rn(S[ch * 8 + j][row] * iv);
            long long o = (long long)(n0 + row) * D + kt * 64 + ch * 8;
            *(uint4*)&d_Wtf16[o] = *(const uint4*)h8;
        }
        __syncthreads();
    }
}

// ---------------- fp16 mma.sync GEMM + fused exp-sum ----------------
// BM=128, BN=256, BK=64, 512 threads (16 warps 4x4), warp tile 32x64.
#define STRIDE 144                         // bytes per 64-k fp16 row (128 data + 16 pad)
#define SM_A 0
#define SM_B (128 * STRIDE)                // 18432
#define STAGE (SM_B + 256 * STRIDE)        // 55296

__global__ void __launch_bounds__(512, 1)
k_mma_sumexp() {
    extern __shared__ char smem[];
    __shared__ float srow[128];
    const uint32_t sbase = smem_u32(smem);
    const int tid = threadIdx.x;
    const int wid = tid >> 5;
    const int lane = tid & 31;
    const int warp_m = wid >> 2;          // 0..3 (32 rows)
    const int warp_n = wid & 3;           // 0..3 (64 cols)
    const int n0 = blockIdx.x * 256;
    const int m0 = blockIdx.y * 128;

    if (tid < 128) srow[tid] = 0.f;

    auto load_stage = [&](int c, int buf) {
        const int k0 = c * 64;
        uint32_t sb = sbase + buf * STAGE;
        #pragma unroll
        for (int i = 0; i < 2; i++) {
            int idx = i * 512 + tid;
            int row = idx >> 3, ch = idx & 7;
            cp16(sb + SM_A + row * STRIDE + ch * 16,
                 d_Af16 + (size_t)(m0 + row) * D + k0 + ch * 8);
        }
        #pragma unroll
        for (int i = 0; i < 4; i++) {
            int idx = i * 512 + tid;
            int row = idx >> 3, ch = idx & 7;
            cp16(sb + SM_B + row * STRIDE + ch * 16,
                 d_Wtf16 + (size_t)(n0 + row) * D + k0 + ch * 8);
        }
    };

    float acc[2][8][4];
    #pragma unroll
    for (int i = 0; i < 2; i++)
        #pragma unroll
        for (int j = 0; j < 8; j++)
            #pragma unroll
            for (int q = 0; q < 4; q++) acc[i][j][q] = 0.f;

    load_stage(0, 0);
    CP_COMMIT();

    const int grp = lane >> 3;            // 0..3
    const int rr = lane & 7;

    for (int c = 0; c < 8; c++) {
        if (c + 1 < 8) { load_stage(c + 1, (c + 1) & 1); CP_COMMIT(); CP_WAIT(1); }
        else           { CP_WAIT(0); }
        __syncthreads();
        uint32_t sb = sbase + (c & 1) * STAGE;
        #pragma unroll
        for (int k16 = 0; k16 < 4; k16++) {
            uint32_t a[2][4], b[4][4];
            #pragma unroll
            for (int mt = 0; mt < 2; mt++) {
                uint32_t rowa = warp_m * 32 + mt * 16 + ((grp & 1) << 3) + rr;
                uint32_t cha = (k16 << 1) + (grp >> 1);
                LDSM4(a[mt][0], a[mt][1], a[mt][2], a[mt][3],
                      sb + SM_A + rowa * STRIDE + cha * 16);
            }
            #pragma unroll
            for (int np = 0; np < 4; np++) {
                uint32_t rowb = warp_n * 64 + np * 16 + ((grp >> 1) << 3) + rr;
                uint32_t chb = (k16 << 1) + (grp & 1);
                LDSM4(b[np][0], b[np][1], b[np][2], b[np][3],
                      sb + SM_B + rowb * STRIDE + chb * 16);
            }
            #pragma unroll
            for (int mt = 0; mt < 2; mt++) {
                #pragma unroll
                for (int nt = 0; nt < 8; nt++) {
                    int pair = nt >> 1, lh = (nt & 1) << 1;
                    MMA16816F(acc[mt][nt], a[mt], b[pair][lh], b[pair][lh + 1]);
                }
            }
        }
        __syncthreads();
    }

    // epilogue
    const int qrow = lane >> 2;
    const int qcol = (lane & 3) << 1;
    #pragma unroll
    for (int mt = 0; mt < 2; mt++) {
        float s_lo = 0.f, s_hi = 0.f;
        #pragma unroll
        for (int nt = 0; nt < 8; nt++) {
            int n = n0 + warp_n * 64 + nt * 8 + qcol;
            if (n < NCLS)     { s_lo += expf(SCALE * acc[mt][nt][0] - SCALE);
                                s_hi += expf(SCALE * acc[mt][nt][2] - SCALE); }
            if (n + 1 < NCLS) { s_lo += expf(SCALE * acc[mt][nt][1] - SCALE);
                                s_hi += expf(SCALE * acc[mt][nt][3] - SCALE); }
        }
        s_lo += __shfl_xor_sync(0xffffffff, s_lo, 1);
        s_lo += __shfl_xor_sync(0xffffffff, s_lo, 2);
        s_hi += __shfl_xor_sync(0xffffffff, s_hi, 1);
        s_hi += __shfl_xor_sync(0xffffffff, s_hi, 2);
        if ((lane & 3) == 0) {
            atomicAdd(&srow[warp_m * 32 + mt * 16 + qrow], s_lo);
            atomicAdd(&srow[warp_m * 32 + mt * 16 + qrow + 8], s_hi);
        }
    }
    __syncthreads();
    if (tid < 128) atomicAdd(&d_rowsum[m0 + tid], srow[tid]);
}

// ---------------- label logits: one warp per row (exact fp32) ----------------
__global__ void k_label_logits(const float* __restrict__ W, const int* __restrict__ labels) {
    int warp = (blockIdx.x * blockDim.x + threadIdx.x) >> 5;
    int lane = threadIdx.x & 31;
    if (warp >= M_TOT) return;
    int lab = labels[warp & 255];
    float ss = 0.f;
    for (int d = lane; d < D; d += 32) ss += d_An[warp * D + d] * W[d * NCLS + lab];
    #pragma unroll
    for (int o = 16; o > 0; o >>= 1) ss += __shfl_xor_sync(0xffffffff, ss, o);
    if (lane == 0) d_lablogit[warp] = SCALE * ss * d_invw[lab];
}

// ---------------- similarity matrices (5 parts + global), fp32 ----------------
__global__ void __launch_bounds__(256)
k_sims() {
    const int s = blockIdx.z;
    const float* Ap = (s < 5) ? (d_pen + s * B * D) : d_An;
    const float* Bp = (s < 5) ? (d_aen + s * B * D) : (d_An + 256 * D);
    __shared__ float As[32][64];
    __shared__ float Bs[32][68];
    const int tx = threadIdx.x & 15;
    const int ty = threadIdx.x >> 4;
    const int m0 = blockIdx.y * 64;
    const int n0 = blockIdx.x * 64;
    float acc[4][4];
    #pragma unroll
    for (int i = 0; i < 4; i++)
        #pragma unroll
        for (int j = 0; j < 4; j++) acc[i][j] = 0.f;

    for (int k0 = 0; k0 < D; k0 += 32) {
        #pragma unroll
        for (int i = 0; i < 2; i++) {
            int li = threadIdx.x + i * 256;
            int m = li >> 3;
            int kk = (li & 7) * 4;
            float4 va = *(const float4*)(Ap + (m0 + m) * D + k0 + kk);
            As[kk + 0][m] = va.x; As[kk + 1][m] = va.y;
            As[kk + 2][m] = va.z; As[kk + 3][m] = va.w;
            float4 vb = *(const float4*)(Bp + (n0 + m) * D + k0 + kk);
            Bs[kk + 0][m] = vb.x; Bs[kk + 1][m] = vb.y;
            Bs[kk + 2][m] = vb.z; Bs[kk + 3][m] = vb.w;
        }
        __syncthreads();
        #pragma unroll
        for (int k = 0; k < 32; k++) {
            float a[4], b[4];
            #pragma unroll
            for (int i = 0; i < 4; i++) a[i] = As[k][ty * 4 + i];
            #pragma unroll
            for (int j = 0; j < 4; j++) b[j] = Bs[k][tx * 4 + j];
            #pragma unroll
            for (int i = 0; i < 4; i++)
                #pragma unroll
                for (int j = 0; j < 4; j++) acc[i][j] = fmaf(a[i], b[j], acc[i][j]);
        }
        __syncthreads();
    }
    #pragma unroll
    for (int i = 0; i < 4; i++)
        #pragma unroll
        for (int j = 0; j < 4; j++)
            d_sim[s * (B * B) + (m0 + ty * 4 + i) * B + n0 + tx * 4 + j] = acc[i][j];
}

// ---------------- top-8 boost flags ----------------
__global__ void k_topk() {
    int p = blockIdx.x;
    const float* S = d_sim + p * (B * B);
    __shared__ int f1[8], f2[8];
    for (int c = threadIdx.x; c < B; c += 32) {
        d_boost1[p * B + c] = 0;
        d_boost2[p * B + c] = 0;
    }
    if (threadIdx.x == 0 || threadIdx.x == 1) {
        bool colmode = (threadIdx.x == 1);
        float val[8]; int idx[8];
        #pragma unroll
        for (int t = 0; t < 8; t++) { val[t] = -1e30f; idx[t] = -1; }
        for (int c = 0; c < B; c++) {
            float v = colmode ? S[c * B + p] : S[p * B + c];
            if (v > val[7]) {
                int j = 7;
                while (j > 0 && v > val[j - 1]) { val[j] = val[j - 1]; idx[j] = idx[j - 1]; j--; }
                val[j] = v; idx[j] = c;
            }
        }
        int* f = colmode ? f2 : f1;
        #pragma unroll
        for (int t = 0; t < 8; t++) f[t] = idx[t];
    }
    __syncthreads();
    if (threadIdx.x < 8) {
        int j = f1[threadIdx.x];
        float ref = S[p * B + j];
        int cnt = 0;
        for (int k = 0; k < B; k++) {
            float v = S[k * B + j];
            if (v > ref || (v == ref && k < p)) cnt++;
        }
        if (cnt < TOPK) d_boost1[p * B + j] = 1;
    } else if (threadIdx.x < 16) {
        int j = f2[threadIdx.x - 8];
        float ref = S[j * B + p];
        int cnt = 0;
        for (int k = 0; k < B; k++) {
            float v = S[j * B + k];
            if (v > ref || (v == ref && k < p)) cnt++;
        }
        if (cnt < TOPK) d_boost2[p * B + j] = 1;
    }
}

// ---------------- align losses reduce ----------------
__global__ void k_align(const int* __restrict__ labels, const int* __restrict__ vmask,
                        const int* __restrict__ tmask) {
    int s = blockIdx.x >> 8;
    int r = blockIdx.x & 255;
    int c = threadIdx.x;
    float v = d_sim[s * (B * B) + r * B + c];
    bool match = (labels[c] == labels[r]);
    float Lp = softplusf(-SPC * (v - ALPHA));
    float Ln = softplusf( SNC * (v - BETA));
    float contrib;
    if (s == 5) {
        contrib = match ? Lp : Ln;
    } else {
        int p = s;
        bool vr = vmask[r * P + p] != 0;
        bool vc = vmask[c * P + p] != 0, tc = tmask[c * P + p] != 0;
        float t1 = (vr && tc) ? ((match || d_boost1[p * B + c]) ? Lp : Ln) : 0.f;
        float t2 = ((vc && tc) && vr) ? ((match || d_boost2[p * B + r]) ? Lp : Ln) : 0.f;
        contrib = t1 + t2;
    }
    __shared__ float red[256];
    red[c] = contrib;
    __syncthreads();
    #pragma unroll
    for (int o = 128; o > 0; o >>= 1) {
        if (c < o) red[c] += red[c + o];
        __syncthreads();
    }
    if (c == 0) atomicAdd(&d_acc[(s == 5) ? 1 : 2], red[0]);
}

// ---------------- mask loss: softmax CE over 6 channels (4 px / thread) ----------------
__global__ void __launch_bounds__(256)
k_mask(const float* __restrict__ seg, const int* __restrict__ masks) {
    int i0 = (blockIdx.x * 256 + threadIdx.x) * 4;
    const float* base = seg + (size_t)(i0 >> 12) * (SEGC * HH) + (i0 & 4095);
    float xs[SEGC][4];
    #pragma unroll
    for (int ch = 0; ch < SEGC; ch++) {
        float4 v = *(const float4*)(base + ch * HH);
        xs[ch][0] = v.x; xs[ch][1] = v.y; xs[ch][2] = v.z; xs[ch][3] = v.w;
    }
    int4 mk = *(const int4*)(masks + i0);
    int mks[4] = {mk.x, mk.y, mk.z, mk.w};
    float ce = 0.f;
    #pragma unroll
    for (int j = 0; j < 4; j++) {
        float m = xs[0][j];
        #pragma unroll
        for (int ch = 1; ch < SEGC; ch++) m = fmaxf(m, xs[ch][j]);
        float ssum = 0.f;
        #pragma unroll
        for (int ch = 0; ch < SEGC; ch++) ssum += expf(xs[ch][j] - m);
        ce += m + logf(ssum) - xs[mks[j]][j];
    }
    __shared__ float red[256];
    red[threadIdx.x] = ce;
    __syncthreads();
    #pragma unroll
    for (int o = 128; o > 0; o >>= 1) {
        if (threadIdx.x < o) red[threadIdx.x] += red[threadIdx.x + o];
        __syncthreads();
    }
    if (threadIdx.x == 0) atomicAdd(&d_acc[0], red[0]);
}

// ---------------- finalize ----------------
__global__ void k_finalize(float* __restrict__ out) {
    __shared__ float sv[M_TOT];
    int t = threadIdx.x;
    sv[t] = SCALE + logf(d_rowsum[t]) - d_lablogit[t];
    __syncthreads();
    if (t == 0) {
        float svl = 0.f, stl = 0.f;
        for (int i = 0; i < 256; i++) { svl += sv[i]; stl += sv[i + 256]; }
        out[0] = svl / 256.f + stl / 256.f;
        out[1] = (float)P * d_acc[0] / (float)NPIX;
        out[2] = 2.f * d_acc[1] / 256.f;
        out[3] = d_acc[2] / (256.f * (float)P);
    }
}

extern "C" void kernel_launch(void* const* d_in, const int* in_sizes, int n_in,
                              void* d_out, int out_size) {
    const float* vis   = (const float*)d_in[0];
    const float* txt   = (const float*)d_in[1];
    const float* pe    = (const float*)d_in[2];
    const float* ae    = (const float*)d_in[3];
    const float* seg   = (const float*)d_in[4];
    const float* W     = (const float*)d_in[5];
    const int*   labels= (const int*)d_in[6];
    const int*   masks = (const int*)d_in[7];
    const int*   vmask = (const int*)d_in[8];
    const int*   tmask = (const int*)d_in[9];
    float* out = (float*)d_out;

    static cudaStream_t s1 = nullptr, s2 = nullptr;
    static cudaEvent_t ef1, ef2, ej1, ej2;
    if (!s1) {
        cudaStreamCreateWithFlags(&s1, cudaStreamNonBlocking);
        cudaStreamCreateWithFlags(&s2, cudaStreamNonBlocking);
        cudaEventCreateWithFlags(&ef1, cudaEventDisableTiming);
        cudaEventCreateWithFlags(&ef2, cudaEventDisableTiming);
        cudaEventCreateWithFlags(&ej1, cudaEventDisableTiming);
        cudaEventCreateWithFlags(&ej2, cudaEventDisableTiming);
        cudaFuncSetAttribute(k_mma_sumexp, cudaFuncAttributeMaxDynamicSharedMemorySize, 2 * STAGE);
    }

    // launch 0
    k_init<<<1, 512>>>();

    // fork: mask loss (launch 1, s1)
    cudaEventRecord(ef1, 0);
    cudaStreamWaitEvent(s1, ef1, 0);
    k_mask<<<NPIX / 1024, 256, 0, s1>>>(seg, masks);
    cudaEventRecord(ej1, s1);

    // launch 2
    k_normalize<<<(3072 * 32 + 255) / 256, 256>>>(vis, txt, pe, ae);
    cudaEventRecord(ef2, 0);   // fork point for sims chain (recorded now, used later)

    // launch 3: merged W prep
    k_wprep<<<NPAD / 128, 512>>>(W);

    // launch 4
    k_label_logits<<<(M_TOT * 32 + 255) / 256, 256>>>(W, labels);

    // launch 5: the big GEMM (ncu -s 5 -c 1 profiles this one)
    {
        dim3 g(NPAD / 256, M_TOT / 128);
        k_mma_sumexp<<<g, 512, 2 * STAGE>>>();
    }

    // sims chain on s2 (launches 6..8), forked after normalize
    cudaStreamWaitEvent(s2, ef2, 0);
    {
        dim3 g(B / 64, B / 64, 6);
        k_sims<<<g, 256, 0, s2>>>();
    }
    k_topk<<<P, 32, 0, s2>>>();
    k_align<<<6 * B, 256, 0, s2>>>(labels, vmask, tmask);
    cudaEventRecord(ej2, s2);

    // join + finalize (launch 9)
    cudaStreamWaitEvent(0, ej1, 0);
    cudaStreamWaitEvent(0, ej2, 0);
    k_finalize<<<1, M_TOT>>>(out);
}

// round 8
// speedup vs baseline: 1.2007x; 1.2007x over previous
#include <cuda_runtime.h>
#include <cuda_fp16.h>
#include <cstdint>
#include <math.h>

#define B 256
#define D 512
#define P 5
#define NCLS 11003
#define NPAD 11008        // 86 * 128
#define SEGC 6
#define HH 4096           // 64*64
#define NPIX (1280*4096)  // B*P*H*H
#define SCALE 28.0f
#define ALPHA 0.6f
#define BETA 0.4f
#define SPC 10.0f
#define SNC 40.0f
#define TOPK 8
#define M_TOT 512         // 256 visual rows + 256 textual rows

// ---------------- scratch (device globals; no allocation) ----------------
__device__ float d_An[M_TOT * D];                  // rows 0..255 = vn, 256..511 = tn
__device__ __align__(16) __half d_Af16[M_TOT * D];
__device__ __align__(16) __half d_Wtf16[NPAD * D]; // [n][k] transposed, UNSCALED
// sims operands: slots 0..4 = parts, slot 5 = (vn, tn); hi/lo fp16 split
__device__ __align__(16) __half d_sAh[6 * B * D];
__device__ __align__(16) __half d_sAl[6 * B * D];
__device__ __align__(16) __half d_sBh[6 * B * D];
__device__ __align__(16) __half d_sBl[6 * B * D];
__device__ float d_invw[NPAD];
__device__ float d_rowsum[M_TOT];
__device__ float d_lablogit[M_TOT];
__device__ float d_sim[6 * B * B];
__device__ int   d_boost1[P * B];
__device__ int   d_boost2[P * B];
__device__ float d_acc[8];                         // 0: mask, 1: global, 2: local

__device__ __forceinline__ float softplusf(float x) {
    return fmaxf(x, 0.f) + log1pf(expf(-fabsf(x)));
}

__device__ __forceinline__ uint32_t smem_u32(const void* p) {
    uint32_t a;
    asm("{ .reg .u64 t; cvta.to.shared.u64 t, %1; cvt.u32.u64 %0, t; }" : "=r"(a) : "l"(p));
    return a;
}
__device__ __forceinline__ void cp16(uint32_t s, const void* g) {
    asm volatile("cp.async.cg.shared.global [%0], [%1], 16;" :: "r"(s), "l"(g));
}
#define CP_COMMIT() asm volatile("cp.async.commit_group;" ::: "memory")
#define CP_WAIT(n)  asm volatile("cp.async.wait_group %0;" :: "n"(n) : "memory")

#define LDSM4(r0, r1, r2, r3, addr) \
    asm volatile("ldmatrix.sync.aligned.m8n8.x4.shared.b16 {%0,%1,%2,%3}, [%4];" \
                 : "=r"(r0), "=r"(r1), "=r"(r2), "=r"(r3) : "r"(addr))

#define MMA16816F(d, a, b0, b1) \
    asm volatile("mma.sync.aligned.m16n8k16.row.col.f32.f16.f16.f32 " \
                 "{%0,%1,%2,%3},{%4,%5,%6,%7},{%8,%9},{%0,%1,%2,%3};" \
                 : "+f"((d)[0]), "+f"((d)[1]), "+f"((d)[2]), "+f"((d)[3]) \
                 : "r"((a)[0]), "r"((a)[1]), "r"((a)[2]), "r"((a)[3]), "r"(b0), "r"(b1))

// ---------------- init ----------------
__global__ void k_init() {
    int t = threadIdx.x;
    if (t < M_TOT) d_rowsum[t] = 0.f;
    if (t < 8) d_acc[t] = 0.f;
}

// ---------------- normalize rows; emit fp32 An, fp16 An, hi/lo sims operands ----------------
__global__ void k_normalize(const float* __restrict__ vis, const float* __restrict__ txt,
                            const float* __restrict__ pe, const float* __restrict__ ae) {
    int warp = (blockIdx.x * blockDim.x + threadIdx.x) >> 5;
    int lane = threadIdx.x & 31;
    if (warp >= 3072) return;
    const float* src;
    __half *ph, *pl;
    if (warp < 256) {
        src = vis + warp * D;
        ph = d_sAh + (size_t)(5 * B + warp) * D;
        pl = d_sAl + (size_t)(5 * B + warp) * D;
    } else if (warp < 512) {
        src = txt + (warp - 256) * D;
        ph = d_sBh + (size_t)(5 * B + (warp - 256)) * D;
        pl = d_sBl + (size_t)(5 * B + (warp - 256)) * D;
    } else if (warp < 1792) {
        int q = warp - 512;
        src = pe + (size_t)q * D;
        ph = d_sAh + (size_t)q * D;
        pl = d_sAl + (size_t)q * D;
    } else {
        int q = warp - 1792;
        src = ae + (size_t)q * D;
        ph = d_sBh + (size_t)q * D;
        pl = d_sBl + (size_t)q * D;
    }
    float ss = 0.f;
    for (int d = lane; d < D; d += 32) { float x = src[d]; ss += x * x; }
    #pragma unroll
    for (int o = 16; o > 0; o >>= 1) ss += __shfl_xor_sync(0xffffffff, ss, o);
    float inv = rsqrtf(ss);
    for (int d = lane; d < D; d += 32) {
        float x = src[d] * inv;
        __half h = __float2half_rn(x);
        ph[d] = h;
        pl[d] = __float2half_rn(x - __half2float(h));
        if (warp < 512) {
            d_An[warp * D + d] = x;
            d_Af16[warp * D + d] = h;
        }
    }
}

// ---------------- W prep single pass: transpose to fp16 (unscaled) + column norms ----------------
// 86 blocks x 512 threads; block owns 128 n-columns.
__global__ void __launch_bounds__(512)
k_wprep(const float* __restrict__ W) {
    __shared__ float red[4][128];
    __shared__ float S[64][129];
    int t = threadIdx.x;
    int n0 = blockIdx.x * 128;
    int cc = t & 127;
    float ss = 0.f;
    for (int kt = 0; kt < 8; kt++) {
        #pragma unroll
        for (int i = 0; i < 16; i++) {
            int idx = t + (i << 9);
            int kk = idx >> 7;
            int c = idx & 127;
            int n = n0 + c;
            float v = (n < NCLS) ? W[(kt * 64 + kk) * NCLS + n] : 0.f;
            S[kk][c] = v;
            ss += v * v;          // c == cc for this thread (512 % 128 == 0)
        }
        __syncthreads();
        #pragma unroll
        for (int i = 0; i < 2; i++) {
            int it = t + (i << 9);
            int row = it >> 3;           // 0..127
            int ch = it & 7;             // 8 fp16 = 16B
            __half h8[8];
            #pragma unroll
            for (int j = 0; j < 8; j++)
                h8[j] = __float2half_rn(S[ch * 8 + j][row]);
            long long o = (long long)(n0 + row) * D + kt * 64 + ch * 8;
            *(uint4*)&d_Wtf16[o] = *(const uint4*)h8;
        }
        __syncthreads();
    }
    red[t >> 7][cc] = ss;
    __syncthreads();
    if (t < 128) {
        float s = red[0][cc] + red[1][cc] + red[2][cc] + red[3][cc];
        d_invw[n0 + cc] = ((n0 + cc) < NCLS) ? rsqrtf(s) : 0.f;
    }
}

// ---------------- fp16 mma GEMM + fused exp-sum (invw in epilogue) ----------------
// BM=128, BN=128, BK=64, 256 threads (8 warps 2x4), warp tile 64x32.
#define STRIDE 144
#define SM_A 0
#define SM_B (128 * STRIDE)                // 18432
#define STAGE (SM_B + 128 * STRIDE)        // 36864

__global__ void __launch_bounds__(256, 2)
k_mma_sumexp() {
    extern __shared__ char smem[];
    __shared__ float srow[128];
    const uint32_t sbase = smem_u32(smem);
    const int tid = threadIdx.x;
    const int wid = tid >> 5;
    const int lane = tid & 31;
    const int warp_m = wid >> 2;          // 0..1 (64 rows)
    const int warp_n = wid & 3;           // 0..3 (32 cols)
    const int n0 = blockIdx.x * 128;
    const int m0 = blockIdx.y * 128;

    if (tid < 128) srow[tid] = 0.f;

    auto load_stage = [&](int c, int buf) {
        const int k0 = c * 64;
        uint32_t sb = sbase + buf * STAGE;
        #pragma unroll
        for (int i = 0; i < 4; i++) {
            int idx = i * 256 + tid;
            int row = idx >> 3, ch = idx & 7;
            cp16(sb + SM_A + row * STRIDE + ch * 16,
                 d_Af16 + (size_t)(m0 + row) * D + k0 + ch * 8);
        }
        #pragma unroll
        for (int i = 0; i < 4; i++) {
            int idx = i * 256 + tid;
            int row = idx >> 3, ch = idx & 7;
            cp16(sb + SM_B + row * STRIDE + ch * 16,
                 d_Wtf16 + (size_t)(n0 + row) * D + k0 + ch * 8);
        }
    };

    float acc[4][4][4];
    #pragma unroll
    for (int i = 0; i < 4; i++)
        #pragma unroll
        for (int j = 0; j < 4; j++)
            #pragma unroll
            for (int q = 0; q < 4; q++) acc[i][j][q] = 0.f;

    load_stage(0, 0);
    CP_COMMIT();

    const int grp = lane >> 3;            // 0..3
    const int rr = lane & 7;

    for (int c = 0; c < 8; c++) {
        if (c + 1 < 8) { load_stage(c + 1, (c + 1) & 1); CP_COMMIT(); CP_WAIT(1); }
        else           { CP_WAIT(0); }
        __syncthreads();
        uint32_t sb = sbase + (c & 1) * STAGE;
        #pragma unroll
        for (int k16 = 0; k16 < 4; k16++) {
            uint32_t a[4][4], b[2][4];
            #pragma unroll
            for (int mt = 0; mt < 4; mt++) {
                uint32_t rowa = warp_m * 64 + mt * 16 + ((grp & 1) << 3) + rr;
                uint32_t cha = (k16 << 1) + (grp >> 1);
                LDSM4(a[mt][0], a[mt][1], a[mt][2], a[mt][3],
                      sb + SM_A + rowa * STRIDE + cha * 16);
            }
            #pragma unroll
            for (int np = 0; np < 2; np++) {
                uint32_t rowb = warp_n * 32 + np * 16 + ((grp >> 1) << 3) + rr;
                uint32_t chb = (k16 << 1) + (grp & 1);
                LDSM4(b[np][0], b[np][1], b[np][2], b[np][3],
                      sb + SM_B + rowb * STRIDE + chb * 16);
            }
            #pragma unroll
            for (int mt = 0; mt < 4; mt++) {
                #pragma unroll
                for (int nt = 0; nt < 4; nt++) {
                    int pair = nt >> 1, lh = (nt & 1) << 1;
                    MMA16816F(acc[mt][nt], a[mt], b[pair][lh], b[pair][lh + 1]);
                }
            }
        }
        __syncthreads();
    }

    // epilogue: logit = SCALE*acc*invw[n] - SCALE
    const int qrow = lane >> 2;
    const int qcol = (lane & 3) << 1;
    float iv0[4], iv1[4];
    int nn[4];
    #pragma unroll
    for (int nt = 0; nt < 4; nt++) {
        int n = n0 + warp_n * 32 + nt * 8 + qcol;
        nn[nt] = n;
        iv0[nt] = d_invw[n];
        iv1[nt] = d_invw[n + 1];
    }
    #pragma unroll
    for (int mt = 0; mt < 4; mt++) {
        float s_lo = 0.f, s_hi = 0.f;
        #pragma unroll
        for (int nt = 0; nt < 4; nt++) {
            if (nn[nt] < NCLS) {
                s_lo += expf(SCALE * acc[mt][nt][0] * iv0[nt] - SCALE);
                s_hi += expf(SCALE * acc[mt][nt][2] * iv0[nt] - SCALE);
            }
            if (nn[nt] + 1 < NCLS) {
                s_lo += expf(SCALE * acc[mt][nt][1] * iv1[nt] - SCALE);
                s_hi += expf(SCALE * acc[mt][nt][3] * iv1[nt] - SCALE);
            }
        }
        s_lo += __shfl_xor_sync(0xffffffff, s_lo, 1);
        s_lo += __shfl_xor_sync(0xffffffff, s_lo, 2);
        s_hi += __shfl_xor_sync(0xffffffff, s_hi, 1);
        s_hi += __shfl_xor_sync(0xffffffff, s_hi, 2);
        if ((lane & 3) == 0) {
            atomicAdd(&srow[warp_m * 64 + mt * 16 + qrow], s_lo);
            atomicAdd(&srow[warp_m * 64 + mt * 16 + qrow + 8], s_hi);
        }
    }
    __syncthreads();
    if (tid < 128) atomicAdd(&d_rowsum[m0 + tid], srow[tid]);
}

// ---------------- label logits: fp32 An x contiguous fp16 Wt row ----------------
__global__ void k_label_logits(const int* __restrict__ labels) {
    int warp = (blockIdx.x * blockDim.x + threadIdx.x) >> 5;
    int lane = threadIdx.x & 31;
    if (warp >= M_TOT) return;
    int lab = labels[warp & 255];
    const __half* wr = d_Wtf16 + (size_t)lab * D;
    float ss = 0.f;
    for (int d = lane; d < D; d += 32) ss += d_An[warp * D + d] * __half2float(wr[d]);
    #pragma unroll
    for (int o = 16; o > 0; o >>= 1) ss += __shfl_xor_sync(0xffffffff, ss, o);
    if (lane == 0) d_lablogit[warp] = SCALE * ss * d_invw[lab];
}

// ---------------- sims via fp16 2-split mma: 64x64 tiles, 128 threads ----------------
#define SIM_A_HI 0
#define SIM_A_LO (64 * STRIDE)
#define SIM_B_HI (2 * 64 * STRIDE)
#define SIM_B_LO (3 * 64 * STRIDE)
#define SIM_STAGE (4 * 64 * STRIDE)        // 36864

__global__ void __launch_bounds__(128)
k_sims_mma() {
    extern __shared__ char smem[];
    const uint32_t sbase = smem_u32(smem);
    const int tid = threadIdx.x;
    const int wid = tid >> 5;
    const int lane = tid & 31;
    const int warp_m = wid >> 1;          // 0..1
    const int warp_n = wid & 1;           // 0..1
    const int s = blockIdx.z;
    const int m0 = blockIdx.y * 64;
    const int n0 = blockIdx.x * 64;
    const __half* Ah = d_sAh + (size_t)s * B * D;
    const __half* Al = d_sAl + (size_t)s * B * D;
    const __half* Bh = d_sBh + (size_t)s * B * D;
    const __half* Bl = d_sBl + (size_t)s * B * D;

    auto load_stage = [&](int c, int buf) {
        const int k0 = c * 64;
        uint32_t sb = sbase + buf * SIM_STAGE;
        #pragma unroll
        for (int i = 0; i < 4; i++) {
            int idx = i * 128 + tid;
            int row = idx >> 3, ch = idx & 7;
            uint32_t so = row * STRIDE + ch * 16;
            size_t goA = (size_t)(m0 + row) * D + k0 + ch * 8;
            size_t goB = (size_t)(n0 + row) * D + k0 + ch * 8;
            cp16(sb + SIM_A_HI + so, Ah + goA);
            cp16(sb + SIM_A_LO + so, Al + goA);
            cp16(sb + SIM_B_HI + so, Bh + goB);
            cp16(sb + SIM_B_LO + so, Bl + goB);
        }
    };

    float acc[2][4][4];
    #pragma unroll
    for (int i = 0; i < 2; i++)
        #pragma unroll
        for (int j = 0; j < 4; j++)
            #pragma unroll
            for (int q = 0; q < 4; q++) acc[i][j][q] = 0.f;

    load_stage(0, 0);
    CP_COMMIT();

    const int grp = lane >> 3;
    const int rr = lane & 7;

    for (int c = 0; c < 8; c++) {
        if (c + 1 < 8) { load_stage(c + 1, (c + 1) & 1); CP_COMMIT(); CP_WAIT(1); }
        else           { CP_WAIT(0); }
        __syncthreads();
        uint32_t sb = sbase + (c & 1) * SIM_STAGE;
        #pragma unroll
        for (int k16 = 0; k16 < 4; k16++) {
            uint32_t ah[2][4], al[2][4], bh[2][4], bl[2][4];
            #pragma unroll
            for (int mt = 0; mt < 2; mt++) {
                uint32_t rowa = warp_m * 32 + mt * 16 + ((grp & 1) << 3) + rr;
                uint32_t cha = (k16 << 1) + (grp >> 1);
                uint32_t off = rowa * STRIDE + cha * 16;
                LDSM4(ah[mt][0], ah[mt][1], ah[mt][2], ah[mt][3], sb + SIM_A_HI + off);
                LDSM4(al[mt][0], al[mt][1], al[mt][2], al[mt][3], sb + SIM_A_LO + off);
            }
            #pragma unroll
            for (int np = 0; np < 2; np++) {
                uint32_t rowb = warp_n * 32 + np * 16 + ((grp >> 1) << 3) + rr;
                uint32_t chb = (k16 << 1) + (grp & 1);
                uint32_t off = rowb * STRIDE + chb * 16;
                LDSM4(bh[np][0], bh[np][1], bh[np][2], bh[np][3], sb + SIM_B_HI + off);
                LDSM4(bl[np][0], bl[np][1], bl[np][2], bl[np][3], sb + SIM_B_LO + off);
            }
            #pragma unroll
            for (int mt = 0; mt < 2; mt++) {
                #pragma unroll
                for (int nt = 0; nt < 4; nt++) {
                    int pair = nt >> 1, lh = (nt & 1) << 1;
                    MMA16816F(acc[mt][nt], ah[mt], bh[pair][lh], bh[pair][lh + 1]);
                    MMA16816F(acc[mt][nt], ah[mt], bl[pair][lh], bl[pair][lh + 1]);
                    MMA16816F(acc[mt][nt], al[mt], bh[pair][lh], bh[pair][lh + 1]);
                }
            }
        }
        __syncthreads();
    }

    const int qrow = lane >> 2;
    const int qcol = (lane & 3) << 1;
    #pragma unroll
    for (int mt = 0; mt < 2; mt++) {
        #pragma unroll
        for (int nt = 0; nt < 4; nt++) {
            int m = m0 + warp_m * 32 + mt * 16 + qrow;
            int n = n0 + warp_n * 32 + nt * 8 + qcol;
            float* o = d_sim + (size_t)s * B * B + (size_t)m * B + n;
            o[0] = acc[mt][nt][0];
            o[1] = acc[mt][nt][1];
            o[8 * B] = acc[mt][nt][2];
            o[8 * B + 1] = acc[mt][nt][3];
        }
    }
}

// ---------------- top-8 boost flags ----------------
__global__ void k_topk() {
    int p = blockIdx.x;
    const float* S = d_sim + p * (B * B);
    __shared__ int f1[8], f2[8];
    for (int c = threadIdx.x; c < B; c += 32) {
        d_boost1[p * B + c] = 0;
        d_boost2[p * B + c] = 0;
    }
    if (threadIdx.x == 0 || threadIdx.x == 1) {
        bool colmode = (threadIdx.x == 1);
        float val[8]; int idx[8];
        #pragma unroll
        for (int t = 0; t < 8; t++) { val[t] = -1e30f; idx[t] = -1; }
        for (int c = 0; c < B; c++) {
            float v = colmode ? S[c * B + p] : S[p * B + c];
            if (v > val[7]) {
                int j = 7;
                while (j > 0 && v > val[j - 1]) { val[j] = val[j - 1]; idx[j] = idx[j - 1]; j--; }
                val[j] = v; idx[j] = c;
            }
        }
        int* f = colmode ? f2 : f1;
        #pragma unroll
        for (int t = 0; t < 8; t++) f[t] = idx[t];
    }
    __syncthreads();
    if (threadIdx.x < 8) {
        int j = f1[threadIdx.x];
        float ref = S[p * B + j];
        int cnt = 0;
        for (int k = 0; k < B; k++) {
            float v = S[k * B + j];
            if (v > ref || (v == ref && k < p)) cnt++;
        }
        if (cnt < TOPK) d_boost1[p * B + j] = 1;
    } else if (threadIdx.x < 16) {
        int j = f2[threadIdx.x - 8];
        float ref = S[j * B + p];
        int cnt = 0;
        for (int k = 0; k < B; k++) {
            float v = S[j * B + k];
            if (v > ref || (v == ref && k < p)) cnt++;
        }
        if (cnt < TOPK) d_boost2[p * B + j] = 1;
    }
}

// ---------------- align losses reduce ----------------
__global__ void k_align(const int* __restrict__ labels, const int* __restrict__ vmask,
                        const int* __restrict__ tmask) {
    int s = blockIdx.x >> 8;
    int r = blockIdx.x & 255;
    int c = threadIdx.x;
    float v = d_sim[s * (B * B) + r * B + c];
    bool match = (labels[c] == labels[r]);
    float Lp = softplusf(-SPC * (v - ALPHA));
    float Ln = softplusf( SNC * (v - BETA));
    float contrib;
    if (s == 5) {
        contrib = match ? Lp : Ln;
    } else {
        int p = s;
        bool vr = vmask[r * P + p] != 0;
        bool vc = vmask[c * P + p] != 0, tc = tmask[c * P + p] != 0;
        float t1 = (vr && tc) ? ((match || d_boost1[p * B + c]) ? Lp : Ln) : 0.f;
        float t2 = ((vc && tc) && vr) ? ((match || d_boost2[p * B + r]) ? Lp : Ln) : 0.f;
        contrib = t1 + t2;
    }
    __shared__ float red[256];
    red[c] = contrib;
    __syncthreads();
    #pragma unroll
    for (int o = 128; o > 0; o >>= 1) {
        if (c < o) red[c] += red[c + o];
        __syncthreads();
    }
    if (c == 0) atomicAdd(&d_acc[(s == 5) ? 1 : 2], red[0]);
}

// ---------------- mask loss: softmax CE over 6 channels (4 px / thread) ----------------
__global__ void __launch_bounds__(256)
k_mask(const float* __restrict__ seg, const int* __restrict__ masks) {
    int i0 = (blockIdx.x * 256 + threadIdx.x) * 4;
    const float* base = seg + (size_t)(i0 >> 12) * (SEGC * HH) + (i0 & 4095);
    float xs[SEGC][4];
    #pragma unroll
    for (int ch = 0; ch < SEGC; ch++) {
        float4 v = *(const float4*)(base + ch * HH);
        xs[ch][0] = v.x; xs[ch][1] = v.y; xs[ch][2] = v.z; xs[ch][3] = v.w;
    }
    int4 mk = *(const int4*)(masks + i0);
    int mks[4] = {mk.x, mk.y, mk.z, mk.w};
    float ce = 0.f;
    #pragma unroll
    for (int j = 0; j < 4; j++) {
        float m = xs[0][j];
        #pragma unroll
        for (int ch = 1; ch < SEGC; ch++) m = fmaxf(m, xs[ch][j]);
        float ssum = 0.f;
        #pragma unroll
        for (int ch = 0; ch < SEGC; ch++) ssum += expf(xs[ch][j] - m);
        ce += m + logf(ssum) - xs[mks[j]][j];
    }
    __shared__ float red[256];
    red[threadIdx.x] = ce;
    __syncthreads();
    #pragma unroll
    for (int o = 128; o > 0; o >>= 1) {
        if (threadIdx.x < o) red[threadIdx.x] += red[threadIdx.x + o];
        __syncthreads();
    }
    if (threadIdx.x == 0) atomicAdd(&d_acc[0], red[0]);
}

// ---------------- finalize ----------------
__global__ void k_finalize(float* __restrict__ out) {
    __shared__ float sv[M_TOT];
    int t = threadIdx.x;
    sv[t] = SCALE + logf(d_rowsum[t]) - d_lablogit[t];
    __syncthreads();
    if (t == 0) {
        float svl = 0.f, stl = 0.f;
        for (int i = 0; i < 256; i++) { svl += sv[i]; stl += sv[i + 256]; }
        out[0] = svl / 256.f + stl / 256.f;
        out[1] = (float)P * d_acc[0] / (float)NPIX;
        out[2] = 2.f * d_acc[1] / 256.f;
        out[3] = d_acc[2] / (256.f * (float)P);
    }
}

extern "C" void kernel_launch(void* const* d_in, const int* in_sizes, int n_in,
                              void* d_out, int out_size) {
    const float* vis   = (const float*)d_in[0];
    const float* txt   = (const float*)d_in[1];
    const float* pe    = (const float*)d_in[2];
    const float* ae    = (const float*)d_in[3];
    const float* seg   = (const float*)d_in[4];
    const float* W     = (const float*)d_in[5];
    const int*   labels= (const int*)d_in[6];
    const int*   masks = (const int*)d_in[7];
    const int*   vmask = (const int*)d_in[8];
    const int*   tmask = (const int*)d_in[9];
    float* out = (float*)d_out;

    static cudaStream_t s1 = nullptr, s2 = nullptr;
    static cudaEvent_t ef1, ef2, ej1, ej2;
    if (!s1) {
        cudaStreamCreateWithFlags(&s1, cudaStreamNonBlocking);
        cudaStreamCreateWithFlags(&s2, cudaStreamNonBlocking);
        cudaEventCreateWithFlags(&ef1, cudaEventDisableTiming);
        cudaEventCreateWithFlags(&ef2, cudaEventDisableTiming);
        cudaEventCreateWithFlags(&ej1, cudaEventDisableTiming);
        cudaEventCreateWithFlags(&ej2, cudaEventDisableTiming);
        cudaFuncSetAttribute(k_mma_sumexp, cudaFuncAttributeMaxDynamicSharedMemorySize, 2 * STAGE);
        cudaFuncSetAttribute(k_sims_mma, cudaFuncAttributeMaxDynamicSharedMemorySize, 2 * SIM_STAGE);
    }

    k_init<<<1, 512>>>();

    // fork: mask loss
    cudaEventRecord(ef1, 0);
    cudaStreamWaitEvent(s1, ef1, 0);
    k_mask<<<NPIX / 1024, 256, 0, s1>>>(seg, masks);
    cudaEventRecord(ej1, s1);

    k_normalize<<<(3072 * 32 + 255) / 256, 256>>>(vis, txt, pe, ae);
    cudaEventRecord(ef2, 0);

    // fork: sims -> topk -> align
    cudaStreamWaitEvent(s2, ef2, 0);
    {
        dim3 g(4, 4, 6);
        k_sims_mma<<<g, 128, 2 * SIM_STAGE, s2>>>();
    }
    k_topk<<<P, 32, 0, s2>>>();
    k_align<<<6 * B, 256, 0, s2>>>(labels, vmask, tmask);
    cudaEventRecord(ej2, s2);

    // main chain: instance loss
    k_wprep<<<NPAD / 128, 512>>>(W);
    k_label_logits<<<(M_TOT * 32 + 255) / 256, 256>>>(labels);
    {
        dim3 g(NPAD / 128, M_TOT / 128);
        k_mma_sumexp<<<g, 256, 2 * STAGE>>>();
    }

    cudaStreamWaitEvent(0, ej1, 0);
    cudaStreamWaitEvent(0, ej2, 0);
    k_finalize<<<1, M_TOT>>>(out);
}